// round 1
// baseline (speedup 1.0000x reference)
#include <cuda_runtime.h>
#include <cstdint>

// Problem dims
#define BB   512
#define FP   4096
#define ENCD 64
#define HH   512
#define VV   42
#define SEQL 128
#define H3   1536   // 3*H

// ---------------- scratch (static device allocation; no runtime alloc) ------
// offsets in floats
#define OFF_H1E 0u
#define OFF_H2E 1048576u
#define OFF_H3E 1572864u
#define OFF_MU  1835008u
#define OFF_LV  1867776u
#define OFF_ENC 1900544u
#define OFF_H0  1933312u
#define OFF_H1  2195456u
#define OFF_GI0 2457600u
#define OFF_GH0 3244032u
#define OFF_GI1 4030464u
#define OFF_GH1 4816896u
#define OFF_WF  5603328u
#define OFF_BF  6389760u
#define SCRATCH_FLOATS 6391296u

__device__ float g_scratch[SCRATCH_FLOATS];

// ---------------- generic multi-chunk NT GEMM -------------------------------
// C[m,n] = act( sum_k A[m,k]*W[n,k] + bias[n] )
// A row-major [M,K], W row-major [N,K], C row-major with ldc.
struct Chunk {
    const float* A;
    const float* W;
    const float* bias;
    float* C;
    int N;
    int ldc;
    int relu;
};
struct GemmArgs {
    Chunk ch[4];
    int K;
};

template <int BN, int TN>
__global__ void __launch_bounds__(128) gemm_nt(GemmArgs args) {
    constexpr int BM = 64, BK = 16, TM = 8;
    constexpr int WV = (BN * BK) / (4 * 128);  // float4 per thread for W tile

    const Chunk c = args.ch[blockIdx.z];
    const int n0 = blockIdx.y * BN;
    if (n0 >= c.N) return;
    const int m0 = blockIdx.x * BM;
    const int K = args.K;
    const int tid = threadIdx.x;
    const int tx = tid % (BN / TN);
    const int ty = tid / (BN / TN);

    __shared__ float As[2][BK][BM];
    __shared__ float Ws[2][BK][BN];

    const float* Abase = c.A + (size_t)m0 * K;

    float4 ra[2], rw[WV];

    auto ldA = [&](int kt) {
#pragma unroll
        for (int i = 0; i < 2; i++) {
            int v = tid + i * 128;
            int m = v >> 2, kv = (v & 3) * 4;
            ra[i] = *reinterpret_cast<const float4*>(Abase + (size_t)m * K + kt * BK + kv);
        }
    };
    auto ldW = [&](int kt) {
#pragma unroll
        for (int i = 0; i < WV; i++) {
            int v = tid + i * 128;
            int n = v >> 2, kv = (v & 3) * 4;
            if (n0 + n < c.N)
                rw[i] = *reinterpret_cast<const float4*>(c.W + (size_t)(n0 + n) * K + kt * BK + kv);
            else
                rw[i] = make_float4(0.f, 0.f, 0.f, 0.f);
        }
    };
    auto stA = [&](int st) {
#pragma unroll
        for (int i = 0; i < 2; i++) {
            int v = tid + i * 128;
            int m = v >> 2, kv = (v & 3) * 4;
            As[st][kv + 0][m] = ra[i].x;
            As[st][kv + 1][m] = ra[i].y;
            As[st][kv + 2][m] = ra[i].z;
            As[st][kv + 3][m] = ra[i].w;
        }
    };
    auto stW = [&](int st) {
#pragma unroll
        for (int i = 0; i < WV; i++) {
            int v = tid + i * 128;
            int n = v >> 2, kv = (v & 3) * 4;
            Ws[st][kv + 0][n] = rw[i].x;
            Ws[st][kv + 1][n] = rw[i].y;
            Ws[st][kv + 2][n] = rw[i].z;
            Ws[st][kv + 3][n] = rw[i].w;
        }
    };

    float acc[TM][TN];
#pragma unroll
    for (int i = 0; i < TM; i++)
#pragma unroll
        for (int j = 0; j < TN; j++) acc[i][j] = 0.f;

    const int ktiles = K / BK;
    ldA(0); ldW(0);
    stA(0); stW(0);
    __syncthreads();

    for (int kt = 0; kt < ktiles; kt++) {
        const int st = kt & 1;
        if (kt + 1 < ktiles) { ldA(kt + 1); ldW(kt + 1); }
#pragma unroll
        for (int kk = 0; kk < BK; kk++) {
            float a[TM], b[TN];
            *reinterpret_cast<float4*>(&a[0]) =
                *reinterpret_cast<const float4*>(&As[st][kk][ty * TM]);
            *reinterpret_cast<float4*>(&a[4]) =
                *reinterpret_cast<const float4*>(&As[st][kk][ty * TM + 4]);
#pragma unroll
            for (int j = 0; j < TN; j += 4)
                *reinterpret_cast<float4*>(&b[j]) =
                    *reinterpret_cast<const float4*>(&Ws[st][kk][tx * TN + j]);
#pragma unroll
            for (int i = 0; i < TM; i++)
#pragma unroll
                for (int j = 0; j < TN; j++)
                    acc[i][j] = fmaf(a[i], b[j], acc[i][j]);
        }
        if (kt + 1 < ktiles) {
            stA(st ^ 1); stW(st ^ 1);
            __syncthreads();
        }
    }

#pragma unroll
    for (int i = 0; i < TM; i++) {
        const int m = m0 + ty * TM + i;
#pragma unroll
        for (int j = 0; j < TN; j++) {
            const int n = n0 + tx * TN + j;
            if (n < c.N) {
                float v = acc[i][j] + c.bias[n];
                if (c.relu) v = fmaxf(v, 0.f);
                c.C[(size_t)m * c.ldc + n] = v;
            }
        }
    }
}

// ---------------- small kernels ---------------------------------------------
__device__ __forceinline__ float sigf(float x) { return 1.f / (1.f + expf(-x)); }

__global__ void gru_combine(const float* __restrict__ gi, const float* __restrict__ gh,
                            float* __restrict__ h) {
    int idx = blockIdx.x * blockDim.x + threadIdx.x;
    if (idx >= BB * HH) return;
    int b = idx / HH, j = idx % HH;
    const float* gib = gi + (size_t)b * H3;
    const float* ghb = gh + (size_t)b * H3;
    float r = sigf(gib[j] + ghb[j]);
    float z = sigf(gib[j + HH] + ghb[j + HH]);
    float n = tanhf(gib[j + 2 * HH] + r * ghb[j + 2 * HH]);
    h[idx] = (1.f - z) * n + z * h[idx];
}

__global__ void fill_gi0_k(const float* __restrict__ w_ih0, const float* __restrict__ b_ih0,
                           float* __restrict__ gi0) {
    int idx = blockIdx.x * blockDim.x + threadIdx.x;
    if (idx >= BB * H3) return;
    int j = idx % H3;
    gi0[idx] = w_ih0[j * VV + (VV - 1)] + b_ih0[j];  // one-hot at index 41
}

// Wf[j,k] = sum_v w_ih0[j,v]*d_fc2w[v,k];  bf[j] = b_ih0[j] + sum_v w_ih0[j,v]*d_fc2b[v]
__global__ void fuse_w_k(const float* __restrict__ w_ih0, const float* __restrict__ d_fc2w,
                         const float* __restrict__ d_fc2b, const float* __restrict__ b_ih0,
                         float* __restrict__ Wf, float* __restrict__ bf) {
    __shared__ float w[VV];
    int j = blockIdx.x;
    if (threadIdx.x < VV) w[threadIdx.x] = w_ih0[j * VV + threadIdx.x];
    __syncthreads();
    for (int k = threadIdx.x; k < HH; k += blockDim.x) {
        float s = 0.f;
#pragma unroll
        for (int v = 0; v < VV; v++) s = fmaf(w[v], d_fc2w[v * HH + k], s);
        Wf[(size_t)j * HH + k] = s;
    }
    if (threadIdx.x == 0) {
        float s = b_ih0[j];
#pragma unroll
        for (int v = 0; v < VV; v++) s = fmaf(w[v], d_fc2b[v], s);
        bf[j] = s;
    }
}

__global__ void kld_kernel(const float* __restrict__ mu, const float* __restrict__ lv,
                           float* __restrict__ out) {
    __shared__ float red[1024];
    float s = 0.f;
    for (int i = threadIdx.x; i < BB * ENCD; i += blockDim.x) {
        float m = mu[i], l = lv[i];
        s += 1.f + l - m * m - expf(l);
    }
    red[threadIdx.x] = s;
    __syncthreads();
    for (int off = 512; off > 0; off >>= 1) {
        if (threadIdx.x < off) red[threadIdx.x] += red[threadIdx.x + off];
        __syncthreads();
    }
    if (threadIdx.x == 0) out[0] = -0.5f * red[0] / (float)BB;
}

__global__ void reparam_k(const float* __restrict__ eps, const float* __restrict__ mu,
                          const float* __restrict__ lv, float* __restrict__ enc) {
    int i = blockIdx.x * blockDim.x + threadIdx.x;
    if (i < BB * ENCD) enc[i] = eps[i] * expf(0.5f * lv[i]) + mu[i];
}

__global__ void zero_k(float* __restrict__ p, int n) {
    int i = blockIdx.x * blockDim.x + threadIdx.x;
    if (i < n) p[i] = 0.f;
}

// ---------------- launcher ---------------------------------------------------
extern "C" void kernel_launch(void* const* d_in, const int* in_sizes, int n_in,
                              void* d_out, int out_size) {
    const float* X       = (const float*)d_in[0];
    // d_in[1] = y (unused by the computation)
    const float* eps     = (const float*)d_in[2];
    const float* e_fc1w  = (const float*)d_in[3];
    const float* e_fc1b  = (const float*)d_in[4];
    const float* e_fc2w  = (const float*)d_in[5];
    const float* e_fc2b  = (const float*)d_in[6];
    const float* e_fc3w  = (const float*)d_in[7];
    const float* e_fc3b  = (const float*)d_in[8];
    const float* e_fc41w = (const float*)d_in[9];
    const float* e_fc41b = (const float*)d_in[10];
    const float* e_fc42w = (const float*)d_in[11];
    const float* e_fc42b = (const float*)d_in[12];
    const float* d_fc1w  = (const float*)d_in[13];
    const float* d_fc1b  = (const float*)d_in[14];
    const float* d_fc2w  = (const float*)d_in[15];
    const float* d_fc2b  = (const float*)d_in[16];
    const float* w_ih0   = (const float*)d_in[17];
    const float* b_ih0   = (const float*)d_in[18];
    const float* w_hh0   = (const float*)d_in[19];
    const float* b_hh0   = (const float*)d_in[20];
    const float* w_ih1   = (const float*)d_in[21];
    const float* b_ih1   = (const float*)d_in[22];
    const float* w_hh1   = (const float*)d_in[23];
    const float* b_hh1   = (const float*)d_in[24];

    float* out = (float*)d_out;              // decoded [B, SEQ, V] then kld
    float* kld_out = out + (size_t)BB * SEQL * VV;

    float* S = nullptr;
    cudaGetSymbolAddress((void**)&S, g_scratch);
    float* h1e = S + OFF_H1E;
    float* h2e = S + OFF_H2E;
    float* h3e = S + OFF_H3E;
    float* mu  = S + OFF_MU;
    float* lv  = S + OFF_LV;
    float* enc = S + OFF_ENC;
    float* h0  = S + OFF_H0;
    float* h1  = S + OFF_H1;
    float* gi0 = S + OFF_GI0;
    float* gh0 = S + OFF_GH0;
    float* gi1 = S + OFF_GI1;
    float* gh1 = S + OFF_GH1;
    float* Wf  = S + OFF_WF;
    float* bf  = S + OFF_BF;

    // --- fused output->input weight (independent of encoder) ---
    fuse_w_k<<<H3, 256>>>(w_ih0, d_fc2w, d_fc2b, b_ih0, Wf, bf);

    // --- encoder ---
    {
        GemmArgs a{}; a.K = FP;
        a.ch[0] = {X, e_fc1w, e_fc1b, h1e, 2048, 2048, 1};
        gemm_nt<128, 8><<<dim3(8, 16, 1), 128>>>(a);
    }
    {
        GemmArgs a{}; a.K = 2048;
        a.ch[0] = {h1e, e_fc2w, e_fc2b, h2e, 1024, 1024, 1};
        gemm_nt<128, 8><<<dim3(8, 8, 1), 128>>>(a);
    }
    {
        GemmArgs a{}; a.K = 1024;
        a.ch[0] = {h2e, e_fc3w, e_fc3b, h3e, 512, 512, 1};
        gemm_nt<128, 8><<<dim3(8, 4, 1), 128>>>(a);
    }
    {
        GemmArgs a{}; a.K = 512;
        a.ch[0] = {h3e, e_fc41w, e_fc41b, mu, ENCD, ENCD, 0};
        a.ch[1] = {h3e, e_fc42w, e_fc42b, lv, ENCD, ENCD, 0};
        gemm_nt<128, 8><<<dim3(8, 1, 2), 128>>>(a);
    }
    kld_kernel<<<1, 1024>>>(mu, lv, kld_out);
    reparam_k<<<(BB * ENCD + 255) / 256, 256>>>(eps, mu, lv, enc);
    {
        GemmArgs a{}; a.K = ENCD;
        a.ch[0] = {enc, d_fc1w, d_fc1b, h0, HH, HH, 0};   // lat -> h0 init
        gemm_nt<128, 8><<<dim3(8, 4, 1), 128>>>(a);
    }
    zero_k<<<(BB * HH + 255) / 256, 256>>>(h1, BB * HH);  // h1 init = 0
    fill_gi0_k<<<(BB * H3 + 255) / 256, 256>>>(w_ih0, b_ih0, gi0);  // gi0 for t=0

    // --- GRU decoder: 128 sequential steps ---
    for (int t = 0; t < SEQL; t++) {
        // phase A: everything that depends only on h0_{t-1}, h1_{t-1}
        GemmArgs a{}; a.K = HH;
        int nch;
        if (t == 0) {
            a.ch[0] = {h0, w_hh0, b_hh0, gh0, H3, H3, 0};
            a.ch[1] = {h1, w_hh1, b_hh1, gh1, H3, H3, 0};  // h1=0 -> bias broadcast
            nch = 2;
        } else {
            a.ch[0] = {h1, Wf,    bf,    gi0, H3, H3, 0};  // fused x_t @ w_ih0.T
            a.ch[1] = {h0, w_hh0, b_hh0, gh0, H3, H3, 0};
            a.ch[2] = {h1, w_hh1, b_hh1, gh1, H3, H3, 0};
            a.ch[3] = {h1, d_fc2w, d_fc2b, out + (size_t)(t - 1) * VV, VV, SEQL * VV, 0}; // out_{t-1}
            nch = 4;
        }
        gemm_nt<128, 8><<<dim3(8, 12, nch), 128>>>(a);

        gru_combine<<<(BB * HH + 255) / 256, 256>>>(gi0, gh0, h0);  // h0 <- h0_t

        // phase B: gi1 = h0_t @ w_ih1.T + b_ih1   (64-wide tiles: 192 blocks)
        GemmArgs b{}; b.K = HH;
        b.ch[0] = {h0, w_ih1, b_ih1, gi1, H3, H3, 0};
        gemm_nt<64, 4><<<dim3(8, 24, 1), 128>>>(b);

        gru_combine<<<(BB * HH + 255) / 256, 256>>>(gi1, gh1, h1);  // h1 <- h1_t
    }

    // final output row: out_{SEQ-1} = h1_{SEQ-1} @ d_fc2w.T + b
    {
        GemmArgs a{}; a.K = HH;
        a.ch[0] = {h1, d_fc2w, d_fc2b, out + (size_t)(SEQL - 1) * VV, VV, SEQL * VV, 0};
        gemm_nt<128, 8><<<dim3(8, 1, 1), 128>>>(a);
    }
}

// round 3
// speedup vs baseline: 1.9273x; 1.9273x over previous
#include <cuda_runtime.h>
#include <cuda_bf16.h>
#include <cstdint>

// ---------------------------------------------------------------- dims
#define BB   512
#define FP   4096
#define ENCD 64
#define HH   512
#define VV   42
#define SEQL 128
#define H3   1536

// ---------------------------------------------------------------- fp32 scratch
#define F_MU   0u
#define F_LV   32768u
#define F_H0   65536u
#define F_H1   327680u
#define F_GI0  589824u
#define F_GH0  1376256u
#define F_GI1  2162688u
#define F_GH1  2949120u
#define F_WF   3735552u
#define F_BF   4521984u
#define F_TOTAL 4523520u
__device__ __align__(256) float g_f32[F_TOTAL];

// ---------------------------------------------------------------- bf16 split scratch
// each matrix [R, C] fp32 stored as bf16 [R, 2C] = [hi(0..C-1) | lo(0..C-1)]
#define S_XS     0u           // 512 x 8192
#define S_E1WS   4194304u     // 2048 x 8192
#define S_H1ES   20971520u    // 512 x 4096
#define S_E2WS   23068672u    // 1024 x 4096
#define S_H2ES   27262976u    // 512 x 2048
#define S_E3WS   28311552u    // 512 x 2048
#define S_H3ES   29360128u    // 512 x 1024
#define S_E41S   29884416u    // 64 x 1024
#define S_E42S   29949952u    // 64 x 1024
#define S_ENCS   30015488u    // 512 x 128
#define S_DFC1S  30081024u    // 512 x 128
#define S_H0S    30146560u    // 512 x 1024
#define S_H1S    30670848u    // 512 x 1024
#define S_WFS    31195136u    // 1536 x 1024
#define S_WHH0S  32768000u    // 1536 x 1024
#define S_WHH1S  34340864u    // 1536 x 1024
#define S_WIH1S  35913728u    // 1536 x 1024
#define S_DFC2S  37486592u    // 42 x 1024
#define S_TOTAL  37529600u
__device__ __align__(256) __nv_bfloat16 g_bf[S_TOTAL];

// ---------------------------------------------------------------- PTX helpers
__device__ __forceinline__ uint32_t smem_u32(const void* p) {
    uint32_t a;
    asm("{ .reg .u64 t; cvta.to.shared.u64 t, %1; cvt.u32.u64 %0, t; }" : "=r"(a) : "l"(p));
    return a;
}
__device__ __forceinline__ void cp16(uint32_t dst, const void* src) {
    asm volatile("cp.async.cg.shared.global [%0], [%1], 16;\n" :: "r"(dst), "l"(src));
}
__device__ __forceinline__ void cp16z(uint32_t dst, const void* src, int sz) {
    asm volatile("cp.async.cg.shared.global [%0], [%1], 16, %2;\n"
                 :: "r"(dst), "l"(src), "r"(sz));
}
__device__ __forceinline__ void ldm4(uint32_t* r, uint32_t addr) {
    asm volatile("ldmatrix.sync.aligned.m8n8.x4.shared.b16 {%0,%1,%2,%3}, [%4];\n"
                 : "=r"(r[0]), "=r"(r[1]), "=r"(r[2]), "=r"(r[3]) : "r"(addr));
}
__device__ __forceinline__ void mma16816(float* c, const uint32_t* a, uint32_t b0, uint32_t b1) {
    asm volatile(
        "mma.sync.aligned.m16n8k16.row.col.f32.bf16.bf16.f32 "
        "{%0,%1,%2,%3}, {%4,%5,%6,%7}, {%8,%9}, {%0,%1,%2,%3};\n"
        : "+f"(c[0]), "+f"(c[1]), "+f"(c[2]), "+f"(c[3])
        : "r"(a[0]), "r"(a[1]), "r"(a[2]), "r"(a[3]), "r"(b0), "r"(b1));
}

// ---------------------------------------------------------------- GEMM (bf16x3)
// C[m,n] = act( sum_k Afp32[m,k] * Wfp32[n,k] + bias[n] )
// A, W given as bf16 split matrices [rows, 2K].  K' = 3K via segment remap:
//   seg0: Ah*Wh   seg1: Al*Wh   seg2: Ah*Wl
struct Chunk {
    const __nv_bfloat16* A;    // [M, 2K]
    const __nv_bfloat16* W;    // [N, 2K]
    const float* bias;         // [N]
    float* C;                  // fp32 out (mode&1)
    __nv_bfloat16* Cs;         // split out [M, 2N] (mode&2)
    int N;
    int ldc;
    int mode;                  // 1=fp32 out, 2=split out, 4=relu
    int ntiles;                // ceil(N/128)
};
struct GemmArgs {
    Chunk ch[4];
    int K;                     // original fp32 K (multiple of 32)
};

#define ROWB 80   // padded smem row bytes (32 bf16 data + 16B pad)

template <int BM>
__global__ void __launch_bounds__(256) gemm_mma(GemmArgs args) {
    constexpr int STB = (BM + 128) * ROWB;
    constexpr int MI = BM / 32;          // m16 frags per warp (warp tile m = BM/2)
    extern __shared__ __align__(128) char smbuf[];
    const uint32_t sb = smem_u32(smbuf);
    const int tid = threadIdx.x;
    const int lane = tid & 31, wid = tid >> 5;
    const int wmBase = (wid >> 2) * (BM / 2);
    const int wnBase = (wid & 3) * 32;

    int rem = blockIdx.y, ci = 0;
    while (rem >= args.ch[ci].ntiles) { rem -= args.ch[ci].ntiles; ci++; }
    const Chunk c = args.ch[ci];
    const int n0 = rem * 128;
    const int m0 = blockIdx.x * BM;
    const int K = args.K;
    const int ksub = K >> 5;
    const int Kt = 3 * ksub;
    const int ld2 = 2 * K;

    auto issue = [&](int kt) {
        const int st = kt % 3;
        const int seg = kt / ksub;
        const int kk = kt - seg * ksub;
        const int aCol = kk * 32 + (seg == 1 ? K : 0);
        const int bCol = kk * 32 + (seg == 2 ? K : 0);
        const uint32_t sA = sb + st * STB;
        const uint32_t sB = sA + BM * ROWB;
        if (BM == 128) {
#pragma unroll
            for (int j = 0; j < 2; j++) {
                int v = tid * 2 + j;
                int row = v >> 2, ch = v & 3;
                cp16(sA + row * ROWB + ch * 16,
                     c.A + (size_t)(m0 + row) * ld2 + aCol + ch * 8);
            }
        } else {
            int row = tid >> 2, ch = tid & 3;
            cp16(sA + row * ROWB + ch * 16,
                 c.A + (size_t)(m0 + row) * ld2 + aCol + ch * 8);
        }
#pragma unroll
        for (int j = 0; j < 2; j++) {
            int v = tid * 2 + j;
            int row = v >> 2, ch = v & 3;
            int n = n0 + row;
            int ok = (n < c.N);
            cp16z(sB + row * ROWB + ch * 16,
                  c.W + (size_t)(ok ? n : 0) * ld2 + bCol + ch * 8,
                  ok ? 16 : 0);
        }
        asm volatile("cp.async.commit_group;\n" ::: "memory");
    };

    float acc[MI][4][4];
#pragma unroll
    for (int mi = 0; mi < MI; mi++)
#pragma unroll
        for (int ni = 0; ni < 4; ni++)
#pragma unroll
            for (int q = 0; q < 4; q++) acc[mi][ni][q] = 0.f;

    issue(0);
    issue(1);

    for (int kt = 0; kt < Kt; kt++) {
        asm volatile("cp.async.wait_group 1;\n" ::: "memory");
        __syncthreads();
        if (kt + 2 < Kt) issue(kt + 2);
        else asm volatile("cp.async.commit_group;\n" ::: "memory");

        const int st = kt % 3;
        const uint32_t sA = sb + st * STB;
        const uint32_t sB = sA + BM * ROWB;
#pragma unroll
        for (int kh = 0; kh < 2; kh++) {
            uint32_t a[MI][4], b[2][4];
#pragma unroll
            for (int mi = 0; mi < MI; mi++) {
                uint32_t addr = sA + (wmBase + mi * 16 + (lane & 15)) * ROWB
                              + kh * 32 + ((lane >> 4) * 16);
                ldm4(a[mi], addr);
            }
#pragma unroll
            for (int nj = 0; nj < 2; nj++) {
                int grp = lane >> 3;
                int nrow = wnBase + nj * 16 + ((grp >> 1) * 8) + (lane & 7);
                uint32_t addr = sB + nrow * ROWB + (kh * 16 + (grp & 1) * 8) * 2;
                ldm4(b[nj], addr);
            }
#pragma unroll
            for (int mi = 0; mi < MI; mi++)
#pragma unroll
                for (int ni = 0; ni < 4; ni++)
                    mma16816(acc[mi][ni], a[mi],
                             b[ni >> 1][(ni & 1) * 2], b[ni >> 1][(ni & 1) * 2 + 1]);
        }
    }

    // ---------------- epilogue ----------------
    const bool wf  = (c.mode & 1) != 0;
    const bool wsp = (c.mode & 2) != 0;
    const bool rel = (c.mode & 4) != 0;
#pragma unroll
    for (int mi = 0; mi < MI; mi++) {
        const int mrow = m0 + wmBase + mi * 16 + (lane >> 2);
#pragma unroll
        for (int ni = 0; ni < 4; ni++) {
            const int n = n0 + wnBase + ni * 8 + (lane & 3) * 2;
#pragma unroll
            for (int half = 0; half < 2; half++) {
                const int mm = mrow + half * 8;
                float v0 = acc[mi][ni][half * 2 + 0];
                float v1 = acc[mi][ni][half * 2 + 1];
                if (n < c.N) v0 += c.bias[n];
                if (n + 1 < c.N) v1 += c.bias[n + 1];
                if (rel) { v0 = fmaxf(v0, 0.f); v1 = fmaxf(v1, 0.f); }
                if (wf) {
                    if (n < c.N)     c.C[(size_t)mm * c.ldc + n]     = v0;
                    if (n + 1 < c.N) c.C[(size_t)mm * c.ldc + n + 1] = v1;
                }
                if (wsp && n + 1 < c.N) {
                    __nv_bfloat16 h0 = __float2bfloat16(v0);
                    __nv_bfloat16 h1 = __float2bfloat16(v1);
                    __nv_bfloat16 l0 = __float2bfloat16(v0 - __bfloat162float(h0));
                    __nv_bfloat16 l1 = __float2bfloat16(v1 - __bfloat162float(h1));
                    __nv_bfloat162 hv; hv.x = h0; hv.y = h1;
                    __nv_bfloat162 lv2; lv2.x = l0; lv2.y = l1;
                    *(__nv_bfloat162*)(c.Cs + (size_t)mm * (2 * c.N) + n) = hv;
                    *(__nv_bfloat162*)(c.Cs + (size_t)mm * (2 * c.N) + c.N + n) = lv2;
                }
            }
        }
    }
}

// ---------------------------------------------------------------- small kernels
__device__ __forceinline__ float sigf(float x) { return 1.f / (1.f + expf(-x)); }

__global__ void split_k(const float* __restrict__ src, __nv_bfloat16* __restrict__ dst,
                        int R, int C) {
    int i = blockIdx.x * blockDim.x + threadIdx.x;
    if (i >= R * C) return;
    int r = i / C, cc = i % C;
    float x = src[i];
    __nv_bfloat16 h = __float2bfloat16(x);
    dst[(size_t)r * 2 * C + cc] = h;
    dst[(size_t)r * 2 * C + C + cc] = __float2bfloat16(x - __bfloat162float(h));
}

__global__ void gru_combine(const float* __restrict__ gi, const float* __restrict__ gh,
                            float* __restrict__ h, __nv_bfloat16* __restrict__ hs) {
    int idx = blockIdx.x * blockDim.x + threadIdx.x;
    if (idx >= BB * HH) return;
    int b = idx / HH, j = idx % HH;
    const float* gib = gi + (size_t)b * H3;
    const float* ghb = gh + (size_t)b * H3;
    float r = sigf(gib[j] + ghb[j]);
    float z = sigf(gib[j + HH] + ghb[j + HH]);
    float n = tanhf(gib[j + 2 * HH] + r * ghb[j + 2 * HH]);
    float v = (1.f - z) * n + z * h[idx];
    h[idx] = v;
    __nv_bfloat16 hi = __float2bfloat16(v);
    hs[(size_t)b * 2 * HH + j] = hi;
    hs[(size_t)b * 2 * HH + HH + j] = __float2bfloat16(v - __bfloat162float(hi));
}

__global__ void fill_gi0_k(const float* __restrict__ w_ih0, const float* __restrict__ b_ih0,
                           float* __restrict__ gi0) {
    int idx = blockIdx.x * blockDim.x + threadIdx.x;
    if (idx >= BB * H3) return;
    int j = idx % H3;
    gi0[idx] = w_ih0[j * VV + (VV - 1)] + b_ih0[j];  // one-hot at index 41
}

__global__ void fuse_w_k(const float* __restrict__ w_ih0, const float* __restrict__ d_fc2w,
                         const float* __restrict__ d_fc2b, const float* __restrict__ b_ih0,
                         float* __restrict__ Wf, float* __restrict__ bf) {
    __shared__ float w[VV];
    int j = blockIdx.x;
    if (threadIdx.x < VV) w[threadIdx.x] = w_ih0[j * VV + threadIdx.x];
    __syncthreads();
    for (int k = threadIdx.x; k < HH; k += blockDim.x) {
        float s = 0.f;
#pragma unroll
        for (int v = 0; v < VV; v++) s = fmaf(w[v], d_fc2w[v * HH + k], s);
        Wf[(size_t)j * HH + k] = s;
    }
    if (threadIdx.x == 0) {
        float s = b_ih0[j];
#pragma unroll
        for (int v = 0; v < VV; v++) s = fmaf(w[v], d_fc2b[v], s);
        bf[j] = s;
    }
}

__global__ void kld_kernel(const float* __restrict__ mu, const float* __restrict__ lv,
                           float* __restrict__ out) {
    __shared__ float red[1024];
    float s = 0.f;
    for (int i = threadIdx.x; i < BB * ENCD; i += blockDim.x) {
        float m = mu[i], l = lv[i];
        s += 1.f + l - m * m - expf(l);
    }
    red[threadIdx.x] = s;
    __syncthreads();
    for (int off = 512; off > 0; off >>= 1) {
        if (threadIdx.x < off) red[threadIdx.x] += red[threadIdx.x + off];
        __syncthreads();
    }
    if (threadIdx.x == 0) out[0] = -0.5f * red[0] / (float)BB;
}

__global__ void reparam_k(const float* __restrict__ eps, const float* __restrict__ mu,
                          const float* __restrict__ lv, __nv_bfloat16* __restrict__ encs) {
    int i = blockIdx.x * blockDim.x + threadIdx.x;
    if (i >= BB * ENCD) return;
    float v = eps[i] * expf(0.5f * lv[i]) + mu[i];
    int b = i / ENCD, j = i % ENCD;
    __nv_bfloat16 h = __float2bfloat16(v);
    encs[(size_t)b * 2 * ENCD + j] = h;
    encs[(size_t)b * 2 * ENCD + ENCD + j] = __float2bfloat16(v - __bfloat162float(h));
}

__global__ void init_h1_k(float* __restrict__ h1, __nv_bfloat16* __restrict__ h1s) {
    int i = blockIdx.x * blockDim.x + threadIdx.x;
    if (i < BB * HH) h1[i] = 0.f;
    if (i < BB * 2 * HH) h1s[i] = __float2bfloat16(0.f);
}

// ---------------------------------------------------------------- launcher
#define SMEM128 (3 * (128 + 128) * ROWB)   // 61440
#define SMEM64  (3 * (64 + 128) * ROWB)    // 46080

static inline void launch128(const GemmArgs& a, int nch) {
    int ny = 0;
    for (int i = 0; i < nch; i++) ny += a.ch[i].ntiles;
    gemm_mma<128><<<dim3(4, ny), 256, SMEM128>>>(a);
}
static inline void launch64(const GemmArgs& a, int nch) {
    int ny = 0;
    for (int i = 0; i < nch; i++) ny += a.ch[i].ntiles;
    gemm_mma<64><<<dim3(8, ny), 256, SMEM64>>>(a);
}

extern "C" void kernel_launch(void* const* d_in, const int* in_sizes, int n_in,
                              void* d_out, int out_size) {
    const float* X       = (const float*)d_in[0];
    const float* eps     = (const float*)d_in[2];
    const float* e_fc1w  = (const float*)d_in[3];
    const float* e_fc1b  = (const float*)d_in[4];
    const float* e_fc2w  = (const float*)d_in[5];
    const float* e_fc2b  = (const float*)d_in[6];
    const float* e_fc3w  = (const float*)d_in[7];
    const float* e_fc3b  = (const float*)d_in[8];
    const float* e_fc41w = (const float*)d_in[9];
    const float* e_fc41b = (const float*)d_in[10];
    const float* e_fc42w = (const float*)d_in[11];
    const float* e_fc42b = (const float*)d_in[12];
    const float* d_fc1w  = (const float*)d_in[13];
    const float* d_fc1b  = (const float*)d_in[14];
    const float* d_fc2w  = (const float*)d_in[15];
    const float* d_fc2b  = (const float*)d_in[16];
    const float* w_ih0   = (const float*)d_in[17];
    const float* b_ih0   = (const float*)d_in[18];
    const float* w_hh0   = (const float*)d_in[19];
    const float* b_hh0   = (const float*)d_in[20];
    const float* w_ih1   = (const float*)d_in[21];
    const float* b_ih1   = (const float*)d_in[22];
    const float* w_hh1   = (const float*)d_in[23];
    const float* b_hh1   = (const float*)d_in[24];

    float* out = (float*)d_out;
    float* kld_out = out + (size_t)BB * SEQL * VV;

    cudaFuncSetAttribute(gemm_mma<128>, cudaFuncAttributeMaxDynamicSharedMemorySize, SMEM128);
    cudaFuncSetAttribute(gemm_mma<64>,  cudaFuncAttributeMaxDynamicSharedMemorySize, SMEM64);

    float* F = nullptr;
    __nv_bfloat16* Sb = nullptr;
    cudaGetSymbolAddress((void**)&F, g_f32);
    cudaGetSymbolAddress((void**)&Sb, g_bf);

    float* mu  = F + F_MU;
    float* lv  = F + F_LV;
    float* h0  = F + F_H0;
    float* h1  = F + F_H1;
    float* gi0 = F + F_GI0;
    float* gh0 = F + F_GH0;
    float* gi1 = F + F_GI1;
    float* gh1 = F + F_GH1;
    float* Wf  = F + F_WF;
    float* bf  = F + F_BF;

    __nv_bfloat16* Xs    = Sb + S_XS;
    __nv_bfloat16* e1ws  = Sb + S_E1WS;
    __nv_bfloat16* h1es  = Sb + S_H1ES;
    __nv_bfloat16* e2ws  = Sb + S_E2WS;
    __nv_bfloat16* h2es  = Sb + S_H2ES;
    __nv_bfloat16* e3ws  = Sb + S_E3WS;
    __nv_bfloat16* h3es  = Sb + S_H3ES;
    __nv_bfloat16* e41s  = Sb + S_E41S;
    __nv_bfloat16* e42s  = Sb + S_E42S;
    __nv_bfloat16* encs  = Sb + S_ENCS;
    __nv_bfloat16* dfc1s = Sb + S_DFC1S;
    __nv_bfloat16* h0s   = Sb + S_H0S;
    __nv_bfloat16* h1s   = Sb + S_H1S;
    __nv_bfloat16* wfs   = Sb + S_WFS;
    __nv_bfloat16* whh0s = Sb + S_WHH0S;
    __nv_bfloat16* whh1s = Sb + S_WHH1S;
    __nv_bfloat16* wih1s = Sb + S_WIH1S;
    __nv_bfloat16* dfc2s = Sb + S_DFC2S;

    auto split = [&](const float* s, __nv_bfloat16* d, int R, int C) {
        int n = R * C;
        split_k<<<(n + 255) / 256, 256>>>(s, d, R, C);
    };

    // one-time splits (per launch)
    split(X, Xs, BB, FP);
    split(e_fc1w, e1ws, 2048, FP);
    split(e_fc2w, e2ws, 1024, 2048);
    split(e_fc3w, e3ws, 512, 1024);
    split(e_fc41w, e41s, ENCD, 512);
    split(e_fc42w, e42s, ENCD, 512);
    split(d_fc1w, dfc1s, HH, ENCD);
    split(d_fc2w, dfc2s, VV, HH);
    split(w_hh0, whh0s, H3, HH);
    split(w_hh1, whh1s, H3, HH);
    split(w_ih1, wih1s, H3, HH);
    fuse_w_k<<<H3, 256>>>(w_ih0, d_fc2w, d_fc2b, b_ih0, Wf, bf);
    split(Wf, wfs, H3, HH);

    // --- encoder ---
    {
        GemmArgs a{}; a.K = FP;
        a.ch[0] = {Xs, e1ws, e_fc1b, nullptr, h1es, 2048, 0, 2 | 4, 16};
        launch64(a, 1);
    }
    {
        GemmArgs a{}; a.K = 2048;
        a.ch[0] = {h1es, e2ws, e_fc2b, nullptr, h2es, 1024, 0, 2 | 4, 8};
        launch64(a, 1);
    }
    {
        GemmArgs a{}; a.K = 1024;
        a.ch[0] = {h2es, e3ws, e_fc3b, nullptr, h3es, 512, 0, 2 | 4, 4};
        launch64(a, 1);
    }
    {
        GemmArgs a{}; a.K = 512;
        a.ch[0] = {h3es, e41s, e_fc41b, mu, nullptr, ENCD, ENCD, 1, 1};
        a.ch[1] = {h3es, e42s, e_fc42b, lv, nullptr, ENCD, ENCD, 1, 1};
        launch64(a, 2);
    }
    kld_kernel<<<1, 1024>>>(mu, lv, kld_out);
    reparam_k<<<(BB * ENCD + 255) / 256, 256>>>(eps, mu, lv, encs);
    {
        GemmArgs a{}; a.K = ENCD;
        a.ch[0] = {encs, dfc1s, d_fc1b, h0, h0s, HH, HH, 1 | 2, 4};
        launch64(a, 1);
    }
    init_h1_k<<<(BB * 2 * HH + 255) / 256, 256>>>(h1, h1s);
    fill_gi0_k<<<(BB * H3 + 255) / 256, 256>>>(w_ih0, b_ih0, gi0);

    // --- GRU decoder ---
    for (int t = 0; t < SEQL; t++) {
        GemmArgs a{}; a.K = HH;
        int nch;
        if (t == 0) {
            a.ch[0] = {h0s, whh0s, b_hh0, gh0, nullptr, H3, H3, 1, 12};
            a.ch[1] = {h1s, whh1s, b_hh1, gh1, nullptr, H3, H3, 1, 12};
            nch = 2;
        } else {
            a.ch[0] = {h1s, wfs,   bf,    gi0, nullptr, H3, H3, 1, 12};
            a.ch[1] = {h0s, whh0s, b_hh0, gh0, nullptr, H3, H3, 1, 12};
            a.ch[2] = {h1s, whh1s, b_hh1, gh1, nullptr, H3, H3, 1, 12};
            a.ch[3] = {h1s, dfc2s, d_fc2b, out + (size_t)(t - 1) * VV, nullptr,
                       VV, SEQL * VV, 1, 1};
            nch = 4;
        }
        launch128(a, nch);

        gru_combine<<<(BB * HH + 255) / 256, 256>>>(gi0, gh0, h0, h0s);

        GemmArgs b{}; b.K = HH;
        b.ch[0] = {h0s, wih1s, b_ih1, gi1, nullptr, H3, H3, 1, 12};
        launch64(b, 1);

        gru_combine<<<(BB * HH + 255) / 256, 256>>>(gi1, gh1, h1, h1s);
    }

    {
        GemmArgs a{}; a.K = HH;
        a.ch[0] = {h1s, dfc2s, d_fc2b, out + (size_t)(SEQL - 1) * VV, nullptr,
                   VV, SEQL * VV, 1, 1};
        launch128(a, 1);
    }
}